// round 13
// baseline (speedup 1.0000x reference)
#include <cuda_runtime.h>
#include <cuda_fp16.h>
#include <math.h>
#include <stdint.h>

#define N0 4096
#define D 320
#define NNZMAX 2200000
#define CBLOCKS 128
#define CITERS 30

// ---------------- device global scratch (no allocation allowed) ----------------
__device__ int g_rp[5][N0 + 1];
__device__ int g_ci[5][NNZMAX];
__device__ int g_deg[N0 + 1];
__device__ __align__(16) float g_v[N0];
// write-once per-iteration power-iteration vectors (no L1 staleness: no line rewritten in-launch)
__device__ __align__(16) float g_pv[(CITERS + 1) * N0];
__device__ __align__(16) float g_XC[N0 * D];
__device__ __align__(16) float g_Wh[N0 * D];
__device__ __align__(16) __half g_WhH[N0 * D];
__device__ float g_f1[N0];
__device__ float g_f2[N0];
__device__ __align__(16) float g_orgX[N0 * D];
__device__ __align__(16) float g_down[4][N0 * D];
__device__ __align__(16) float g_Hbuf[N0 * D];
__device__ __align__(16) float g_Ubuf[N0 * D];
__device__ float g_scores[N0];
__device__ float g_vals[N0];
__device__ int g_idx[4][N0];
__device__ int g_rankL[4][N0];
__device__ unsigned g_barcnt = 0;
__device__ unsigned g_bargen = 0;

// ---------------- CSR build from dense A (level 0) ----------------
__global__ void csr0_count(const float* __restrict__ A) {
    int r = blockIdx.x;
    int cnt = 0;
    for (int c = threadIdx.x; c < N0; c += blockDim.x)
        cnt += (A[(size_t)r * N0 + c] > 0.f) ? 1 : 0;
    __shared__ int s[256];
    s[threadIdx.x] = cnt;
    __syncthreads();
    for (int st = 128; st > 0; st >>= 1) {
        if (threadIdx.x < st) s[threadIdx.x] += s[threadIdx.x + st];
        __syncthreads();
    }
    if (threadIdx.x == 0) g_deg[r] = s[0];
}

// single-block exclusive scan of g_deg[0..n) -> rp[0..n]
__global__ void scan_kernel(int* __restrict__ rp, int n) {
    __shared__ int sh[1024];
    int tid = threadIdx.x;
    int loc[4];
    int s = 0;
    int base = tid * 4;
#pragma unroll
    for (int k = 0; k < 4; k++) {
        int i = base + k;
        int vv = (i < n) ? g_deg[i] : 0;
        loc[k] = s;
        s += vv;
    }
    sh[tid] = s;
    __syncthreads();
    for (int off = 1; off < 1024; off <<= 1) {
        int v = (tid >= off) ? sh[tid - off] : 0;
        __syncthreads();
        sh[tid] += v;
        __syncthreads();
    }
    int pre = (tid > 0) ? sh[tid - 1] : 0;
#pragma unroll
    for (int k = 0; k < 4; k++) {
        int i = base + k;
        if (i < n) rp[i] = pre + loc[k];
    }
    if (tid == 1023) rp[n] = sh[1023];
}

__global__ void csr0_fill(const float* __restrict__ A, const int* __restrict__ rp,
                          int* __restrict__ ci) {
    int r = blockIdx.x;
    __shared__ int s_off;
    __shared__ int wcnt[8];
    if (threadIdx.x == 0) s_off = rp[r];
    __syncthreads();
    for (int c0 = 0; c0 < N0; c0 += 256) {
        int c = c0 + threadIdx.x;
        bool nz = (A[(size_t)r * N0 + c] > 0.f);
        unsigned b = __ballot_sync(0xffffffffu, nz);
        int lane = threadIdx.x & 31, w = threadIdx.x >> 5;
        if (lane == 0) wcnt[w] = __popc(b);
        __syncthreads();
        if (threadIdx.x == 0) {
            int a = s_off;
            for (int i = 0; i < 8; i++) {
                int t = wcnt[i];
                wcnt[i] = a;
                a += t;
            }
            s_off = a;
        }
        __syncthreads();
        if (nz) ci[wcnt[w] + __popc(b & ((1u << lane) - 1))] = c;
        __syncthreads();
    }
}

// ---------------- fused centrality (30 power iterations, one kernel) ----------------
// One grid barrier per iteration; every block redundantly recomputes the norm with the
// EXACT 1024-thread tree of the original norm_iter kernel (bit-identical numerics).
__device__ __forceinline__ void grid_barrier() {
    __threadfence();
    __syncthreads();
    if (threadIdx.x == 0) {
        unsigned gen = *((volatile unsigned*)&g_bargen);
        unsigned t = atomicAdd(&g_barcnt, 1u);
        if (t == (unsigned)(CBLOCKS - 1)) {
            g_barcnt = 0;
            __threadfence();
            atomicAdd(&g_bargen, 1u);
        } else {
            while (*((volatile unsigned*)&g_bargen) == gen) {
            }
        }
    }
    __syncthreads();
    __threadfence();
}

__global__ void __launch_bounds__(1024, 1)
centrality_fused(const int* __restrict__ rp, const int* __restrict__ ci) {
    int tid = threadIdx.x;
    int w = tid >> 5, lane = tid & 31;
    int row = blockIdx.x * 32 + w;
    __shared__ float red[1024];
    // seed slice 0 = v0 = 1/N
    if (tid < 32) g_pv[blockIdx.x * 32 + tid] = 1.f / (float)N0;
    grid_barrier();
    float inv = 1.0f;  // multiply-by-1 is exact
    int s = rp[row], e = rp[row + 1];
    for (int t = 0; t < CITERS; t++) {
        const float* bufA = g_pv + (size_t)t * N0;
        float* bufB = g_pv + (size_t)(t + 1) * N0;
        // spmv: bufB[row] = sum_k fl(bufA[ci[k]] * inv)   (== v[ci[k]] of the unfused version)
        float acc = 0.f;
        for (int k = s + lane; k < e; k += 32) acc += __fmul_rn(bufA[ci[k]], inv);
        for (int o = 16; o; o >>= 1) acc += __shfl_down_sync(0xffffffffu, acc, o);
        if (lane == 0) bufB[row] = acc;
        grid_barrier();
        // norm of bufB: identical tree to the original norm_iter (redundant per block)
        float ss = 0.f;
        for (int i = tid; i < N0; i += 1024) {
            float tt = bufB[i];
            ss += tt * tt;
        }
        red[tid] = ss;
        __syncthreads();
        for (int st = 512; st > 0; st >>= 1) {
            if (tid < st) red[tid] += red[tid + st];
            __syncthreads();
        }
        inv = 1.f / (sqrtf(red[0]) + 1e-12f);
        __syncthreads();
    }
    if (tid < 32) {
        int i = blockIdx.x * 32 + tid;
        g_v[i] = __fmul_rn(g_pv[(size_t)CITERS * N0 + i], inv);
    }
}

// ---------------- misc elementwise ----------------
__global__ void concat_xc_kernel(const float* __restrict__ X, const float* __restrict__ v,
                                 float* __restrict__ XC) {
    int i = blockIdx.x * blockDim.x + threadIdx.x;
    if (i >= N0 * D) return;
    int r = i / D, d = i % D;
    XC[i] = (d < D - 1) ? X[(size_t)r * (D - 1) + d] : v[r];
}

// fused unpool: U[r,:] = rank[r]<0 ? 0 : H[rank[r],:] * sigmoid(Z[rank[r],:] + b)
__global__ void unpool_fused_kernel(const float* __restrict__ H, const float* __restrict__ Z,
                                    const float* __restrict__ b, const int* __restrict__ rank,
                                    float* __restrict__ U, int nl) {
    int i = blockIdx.x * blockDim.x + threadIdx.x;
    if (i >= nl * D) return;
    int r = i / D, d = i % D;
    int rk = rank[r];
    float o = 0.f;
    if (rk >= 0) {
        float z = Z[(size_t)rk * D + d] + b[d];
        o = H[(size_t)rk * D + d] * (1.f / (1.f + expf(-z)));
    }
    U[i] = o;
}

__global__ void poolx_kernel(const float* __restrict__ G, const int* __restrict__ idx,
                             const float* __restrict__ vals, float* __restrict__ nx, int nk) {
    int i = blockIdx.x * blockDim.x + threadIdx.x;
    if (i >= nk * D) return;
    int r = i / D, d = i % D;
    nx[i] = G[(size_t)idx[r] * D + d] * vals[r];
}

__global__ void rank_init_kernel(int* __restrict__ rank, int pn) {
    int i = blockIdx.x * blockDim.x + threadIdx.x;
    if (i < pn) rank[i] = -1;
}

__global__ void rank_set_kernel(const int* __restrict__ idx, int* __restrict__ rank, int nk) {
    int i = blockIdx.x * blockDim.x + threadIdx.x;
    if (i < nk) rank[idx[i]] = i;
}

// ---------------- pooled CSR build ----------------
__global__ void pool_deg_kernel(const int* __restrict__ prp, const int* __restrict__ pci,
                                const int* __restrict__ idx, const int* __restrict__ rank,
                                int nk) {
    int w = (blockIdx.x * blockDim.x + threadIdx.x) >> 5;
    if (w >= nk) return;
    int lane = threadIdx.x & 31;
    int p = idx[w];
    int s = prp[p], e = prp[p + 1];
    int cnt = 0;
    for (int k = s + lane; k < e; k += 32) cnt += (rank[pci[k]] >= 0) ? 1 : 0;
    for (int o = 16; o; o >>= 1) cnt += __shfl_down_sync(0xffffffffu, cnt, o);
    if (lane == 0) g_deg[w] = cnt;
}

__global__ void pool_fill_kernel(const int* __restrict__ prp, const int* __restrict__ pci,
                                 const int* __restrict__ nrp, int* __restrict__ nci,
                                 const int* __restrict__ idx, const int* __restrict__ rank,
                                 int nk) {
    int w = (blockIdx.x * blockDim.x + threadIdx.x) >> 5;
    if (w >= nk) return;
    int lane = threadIdx.x & 31;
    int p = idx[w];
    int s = prp[p], e = prp[p + 1];
    int wbase = nrp[w];
    for (int k0 = s; k0 < e; k0 += 32) {
        int k = k0 + lane;
        int rk = -1;
        if (k < e) rk = rank[pci[k]];
        bool keep = (rk >= 0);
        unsigned b = __ballot_sync(0xffffffffu, keep);
        if (keep) nci[wbase + __popc(b & ((1u << lane) - 1))] = rk;
        wbase += __popc(b);
    }
}

// ---------------- pool scoring + sort (top-k) ----------------
__global__ void pool_score_kernel(const float* __restrict__ Xf, const float* __restrict__ pw,
                                  const float* __restrict__ pb, float* __restrict__ scores, int n) {
    int w = (blockIdx.x * blockDim.x + threadIdx.x) >> 5;
    if (w >= n) return;
    int lane = threadIdx.x & 31;
    float s = 0.f;
    for (int d = lane; d < D; d += 32) s += Xf[(size_t)w * D + d] * pw[d];
    for (int o = 16; o; o >>= 1) s += __shfl_down_sync(0xffffffffu, s, o);
    if (lane == 0) {
        float z = (s + pb[0]) / 100.f;
        scores[w] = 1.f / (1.f + expf(-z));
    }
}

// single-block bitonic sort: descending score, ascending index on tie
__global__ void sort_kernel(const float* __restrict__ scores, float* __restrict__ vals,
                            int* __restrict__ idxo, int n, int P) {
    __shared__ float sv[4096];
    __shared__ int si[4096];
    int tid = threadIdx.x;
    for (int i = tid; i < P; i += 1024) {
        bool ok = (i < n);
        sv[i] = ok ? scores[i] : -INFINITY;
        si[i] = ok ? i : 0x7fffffff;
    }
    __syncthreads();
    for (int k = 2; k <= P; k <<= 1) {
        for (int j = k >> 1; j > 0; j >>= 1) {
            for (int i = tid; i < P; i += 1024) {
                int ixj = i ^ j;
                if (ixj > i) {
                    float s1 = sv[i], s2 = sv[ixj];
                    int i1 = si[i], i2 = si[ixj];
                    bool firstBetter = (s1 > s2) || (s1 == s2 && i1 < i2);
                    bool desc = ((i & k) == 0);
                    if (desc ? !firstBetter : firstBetter) {
                        sv[i] = s2;
                        sv[ixj] = s1;
                        si[i] = i2;
                        si[ixj] = i1;
                    }
                }
            }
            __syncthreads();
        }
    }
    for (int i = tid; i < n; i += 1024) {
        vals[i] = sv[i];
        idxo[i] = si[i];
    }
}

// ---------------- GEMM: C[M,N] = A[M,K] @ B ; B is [K,N] or (transB) [N,K] ----------------
// optional Ch: also store fp16 copy of C. A2: optional second A source for gk>=Ksplit.
__global__ void gemm_kernel(const float* __restrict__ A, const float* __restrict__ A2,
                            int Ksplit, const float* __restrict__ B,
                            float* __restrict__ C, __half* __restrict__ Ch,
                            int M, int K, int N, int transB) {
    __shared__ __align__(16) float As[16][68];
    __shared__ __align__(16) float Bs[16][68];
    int bm = blockIdx.y * 64, bn = blockIdx.x * 64;
    int tid = threadIdx.x;
    int tx = tid & 15, ty = tid >> 4;
    float acc[4][4] = {};
    for (int k0 = 0; k0 < K; k0 += 16) {
#pragma unroll
        for (int i = tid; i < 1024; i += 256) {
            int kk = i & 15, m = i >> 4;
            int gm = bm + m, gk = k0 + kk;
            float av = 0.f;
            if (gm < M) {
                if (gk < Ksplit)
                    av = A[(size_t)gm * Ksplit + gk];
                else
                    av = A2[(size_t)gm * Ksplit + (gk - Ksplit)];
            }
            As[kk][m] = av;
        }
        if (!transB) {
#pragma unroll
            for (int i = tid; i < 1024; i += 256) {
                int nn = i & 63, kk = i >> 6;
                int gn = bn + nn, gk = k0 + kk;
                Bs[kk][nn] = (gn < N) ? B[(size_t)gk * N + gn] : 0.f;
            }
        } else {
#pragma unroll
            for (int i = tid; i < 1024; i += 256) {
                int kk = i & 15, nn = i >> 4;
                int gn = bn + nn, gk = k0 + kk;
                Bs[kk][nn] = (gn < N) ? B[(size_t)gn * K + gk] : 0.f;
            }
        }
        __syncthreads();
#pragma unroll
        for (int kk = 0; kk < 16; kk++) {
            float4 a4 = *reinterpret_cast<const float4*>(&As[kk][ty * 4]);
            float4 b4 = *reinterpret_cast<const float4*>(&Bs[kk][tx * 4]);
            float av[4] = {a4.x, a4.y, a4.z, a4.w};
            float bv[4] = {b4.x, b4.y, b4.z, b4.w};
#pragma unroll
            for (int i2 = 0; i2 < 4; i2++)
#pragma unroll
                for (int j2 = 0; j2 < 4; j2++) acc[i2][j2] += av[i2] * bv[j2];
        }
        __syncthreads();
    }
#pragma unroll
    for (int i2 = 0; i2 < 4; i2++) {
        int gm = bm + ty * 4 + i2;
        if (gm < M) {
#pragma unroll
            for (int j2 = 0; j2 < 4; j2++) {
                int gn = bn + tx * 4 + j2;
                if (gn < N) {
                    C[(size_t)gm * N + gn] = acc[i2][j2];
                    if (Ch) Ch[(size_t)gm * N + gn] = __float2half(acc[i2][j2]);
                }
            }
        }
    }
}

// 32x64 tile variant for small M (better wave balance)
__global__ void gemm32_kernel(const float* __restrict__ A, const float* __restrict__ B,
                              float* __restrict__ C, __half* __restrict__ Ch,
                              int M, int K, int N, int transB) {
    __shared__ __align__(16) float As[16][36];
    __shared__ __align__(16) float Bs[16][68];
    int bm = blockIdx.y * 32, bn = blockIdx.x * 64;
    int tid = threadIdx.x;
    int tx = tid & 15, ty = tid >> 4;
    float acc[2][4] = {};
    for (int k0 = 0; k0 < K; k0 += 16) {
#pragma unroll
        for (int i = tid; i < 512; i += 256) {
            int kk = i & 15, m = i >> 4;
            int gm = bm + m, gk = k0 + kk;
            As[kk][m] = (gm < M) ? A[(size_t)gm * K + gk] : 0.f;
        }
        if (!transB) {
#pragma unroll
            for (int i = tid; i < 1024; i += 256) {
                int nn = i & 63, kk = i >> 6;
                int gn = bn + nn, gk = k0 + kk;
                Bs[kk][nn] = (gn < N) ? B[(size_t)gk * N + gn] : 0.f;
            }
        } else {
#pragma unroll
            for (int i = tid; i < 1024; i += 256) {
                int kk = i & 15, nn = i >> 4;
                int gn = bn + nn, gk = k0 + kk;
                Bs[kk][nn] = (gn < N) ? B[(size_t)gn * K + gk] : 0.f;
            }
        }
        __syncthreads();
#pragma unroll
        for (int kk = 0; kk < 16; kk++) {
            float a0 = As[kk][ty * 2];
            float a1 = As[kk][ty * 2 + 1];
            float4 b4 = *reinterpret_cast<const float4*>(&Bs[kk][tx * 4]);
            float bv[4] = {b4.x, b4.y, b4.z, b4.w};
#pragma unroll
            for (int j2 = 0; j2 < 4; j2++) {
                acc[0][j2] += a0 * bv[j2];
                acc[1][j2] += a1 * bv[j2];
            }
        }
        __syncthreads();
    }
#pragma unroll
    for (int i2 = 0; i2 < 2; i2++) {
        int gm = bm + ty * 2 + i2;
        if (gm < M) {
#pragma unroll
            for (int j2 = 0; j2 < 4; j2++) {
                int gn = bn + tx * 4 + j2;
                if (gn < N) {
                    C[(size_t)gm * N + gn] = acc[i2][j2];
                    if (Ch) Ch[(size_t)gm * N + gn] = __float2half(acc[i2][j2]);
                }
            }
        }
    }
}

// ---------------- attention coefficients: f1 = Wh@a[:D], f2 = Wh@a[D:] ----------------
__global__ void attn_coef_kernel(const float* __restrict__ Wh, const float* __restrict__ a,
                                 float* __restrict__ f1, float* __restrict__ f2, int n) {
    int w = (blockIdx.x * blockDim.x + threadIdx.x) >> 5;
    if (w >= n) return;
    int lane = threadIdx.x & 31;
    float s1 = 0.f, s2 = 0.f;
    for (int d = lane; d < D; d += 32) {
        float v = Wh[(size_t)w * D + d];
        s1 += v * a[d];
        s2 += v * a[D + d];
    }
    for (int o = 16; o; o >>= 1) {
        s1 += __shfl_down_sync(0xffffffffu, s1, o);
        s2 += __shfl_down_sync(0xffffffffu, s2, o);
    }
    if (lane == 0) {
        f1[w] = s1;
        f2[w] = s2;
    }
}

// fp16 row accumulate helper: adds p * row (8 halves in a uint4) into acc[8], in order
__device__ __forceinline__ void acc_row8(float* acc, uint4 hv, float pj) {
    __half2 h0 = *reinterpret_cast<__half2*>(&hv.x);
    __half2 h1 = *reinterpret_cast<__half2*>(&hv.y);
    __half2 h2 = *reinterpret_cast<__half2*>(&hv.z);
    __half2 h3 = *reinterpret_cast<__half2*>(&hv.w);
    float2 f0 = __half22float2(h0);
    float2 fb = __half22float2(h1);
    float2 fc = __half22float2(h2);
    float2 fd = __half22float2(h3);
    acc[0] += pj * f0.x;
    acc[1] += pj * f0.y;
    acc[2] += pj * fb.x;
    acc[3] += pj * fb.y;
    acc[4] += pj * fc.x;
    acc[5] += pj * fc.y;
    acc[6] += pj * fd.x;
    acc[7] += pj * fd.y;
}

// ---------------- fused sparse masked softmax + SpMM GAT attention (fp16 values) ----------------
// Softmax weights / reductions stay fp32; only the gathered neighbor rows are fp16.
// Pass-2 gather manually unrolled 4-wide for MLP (accumulation stays j-ascending:
// numerics bit-identical to the non-unrolled version).
// mode: 0 = plain, 1 = elu, 2 = elu + residual add
__global__ void gat_attn_h_kernel(const int* __restrict__ rp, const int* __restrict__ ci,
                                  const float* __restrict__ Wh, const __half* __restrict__ WhH,
                                  const float* __restrict__ f1, const float* __restrict__ f2,
                                  float* __restrict__ out, const float* __restrict__ addsrc,
                                  int n, int mode) {
    int r = blockIdx.x;
    int tid = threadIdx.x;
    __shared__ float s_red[320];
    __shared__ float s_p[320];
    __shared__ int s_c[320];
    __shared__ float s_accf[8 * 320];
    int start = rp[r];
    int deg = rp[r + 1] - start;
    if (deg == 0) {
        float s = 0.f;
        for (int i = 0; i < n; i++) s += Wh[(size_t)i * D + tid];
        float o = s / (float)n;
        if (mode >= 1) o = (o > 0.f) ? o : expm1f(o);
        if (mode == 2) o += addsrc[(size_t)r * D + tid];
        out[(size_t)r * D + tid] = o;
        return;
    }
    float F1 = f1[r];
    float m = -INFINITY;
    for (int k = tid; k < deg; k += 320) {
        float e = F1 + f2[ci[start + k]];
        e = (e > 0.f) ? e : 0.2f * e;
        m = fmaxf(m, e);
    }
    s_red[tid] = m;
    __syncthreads();
    if (tid < 64) s_red[tid] = fmaxf(s_red[tid], s_red[tid + 256]);
    __syncthreads();
    if (tid < 128) s_red[tid] = fmaxf(s_red[tid], s_red[tid + 128]);
    __syncthreads();
    if (tid < 64) s_red[tid] = fmaxf(s_red[tid], s_red[tid + 64]);
    __syncthreads();
    if (tid < 32) {
        float v = fmaxf(s_red[tid], s_red[tid + 32]);
        for (int o = 16; o; o >>= 1) v = fmaxf(v, __shfl_down_sync(0xffffffffu, v, o));
        if (tid == 0) s_red[0] = v;
    }
    __syncthreads();
    m = s_red[0];
    __syncthreads();
    int g = tid / 40, l = tid % 40;
    float acc[8];
#pragma unroll
    for (int c = 0; c < 8; c++) acc[c] = 0.f;
    float Zp = 0.f;
    for (int b0 = 0; b0 < deg; b0 += 320) {
        int k = b0 + tid;
        float p = 0.f;
        int c = 0;
        if (k < deg) {
            c = ci[start + k];
            float e = F1 + f2[c];
            e = (e > 0.f) ? e : 0.2f * e;
            p = __expf(e - m);
        }
        s_p[tid] = p;
        s_c[tid] = c;
        Zp += p;
        __syncthreads();
        int cnt = min(320, deg - b0);
        // 4-wide manual unroll: 4 independent LDG.128 in flight per step.
        // Accumulation order remains strictly j-ascending (bit-identical numerics).
        int j = g;
#pragma unroll 1
        for (; j + 24 < cnt; j += 32) {
            float p0 = s_p[j];
            float p1 = s_p[j + 8];
            float p2 = s_p[j + 16];
            float p3 = s_p[j + 24];
            const uint4* r0 = reinterpret_cast<const uint4*>(WhH + (size_t)s_c[j] * D);
            const uint4* r1 = reinterpret_cast<const uint4*>(WhH + (size_t)s_c[j + 8] * D);
            const uint4* r2 = reinterpret_cast<const uint4*>(WhH + (size_t)s_c[j + 16] * D);
            const uint4* r3 = reinterpret_cast<const uint4*>(WhH + (size_t)s_c[j + 24] * D);
            uint4 hv0 = r0[l];
            uint4 hv1 = r1[l];
            uint4 hv2 = r2[l];
            uint4 hv3 = r3[l];
            acc_row8(acc, hv0, p0);
            acc_row8(acc, hv1, p1);
            acc_row8(acc, hv2, p2);
            acc_row8(acc, hv3, p3);
        }
#pragma unroll 1
        for (; j < cnt; j += 8) {
            float pj = s_p[j];
            const uint4* row = reinterpret_cast<const uint4*>(WhH + (size_t)s_c[j] * D);
            uint4 hv = row[l];
            acc_row8(acc, hv, pj);
        }
        __syncthreads();
    }
    s_red[tid] = Zp;
    __syncthreads();
    if (tid < 64) s_red[tid] += s_red[tid + 256];
    __syncthreads();
    if (tid < 128) s_red[tid] += s_red[tid + 128];
    __syncthreads();
    if (tid < 64) s_red[tid] += s_red[tid + 64];
    __syncthreads();
    if (tid < 32) {
        float v = s_red[tid] + s_red[tid + 32];
        for (int o = 16; o; o >>= 1) v += __shfl_down_sync(0xffffffffu, v, o);
        if (tid == 0) s_red[0] = v;
    }
    __syncthreads();
    float invZ = 1.f / s_red[0];
#pragma unroll
    for (int c = 0; c < 8; c++) s_accf[g * 320 + l * 8 + c] = acc[c];
    __syncthreads();
    {
        int d = tid;
        float o = 0.f;
#pragma unroll
        for (int gg2 = 0; gg2 < 8; gg2++) o += s_accf[gg2 * 320 + d];
        o *= invZ;
        if (mode >= 1) o = (o > 0.f) ? o : expm1f(o);
        if (mode == 2) o += addsrc[(size_t)r * D + d];
        out[(size_t)r * D + d] = o;
    }
}

// ---------------- host ----------------
static void launch_gemm(const float* A, const float* B, float* C, __half* Ch, int M, int K,
                        int N, int transB) {
    if (M < 2048) {
        dim3 gg((N + 63) / 64, (M + 31) / 32);
        gemm32_kernel<<<gg, 256>>>(A, B, C, Ch, M, K, N, transB);
    } else {
        dim3 gg((N + 63) / 64, (M + 63) / 64);
        gemm_kernel<<<gg, 256>>>(A, nullptr, K, B, C, Ch, M, K, N, transB);
    }
}

static void run_gat(const float* Hin, int n, int K, const float* W, const float* avec,
                    const int* rp, const int* ci, float* outp, int mode, const float* add,
                    float* Wh, __half* WhH, float* f1, float* f2) {
    launch_gemm(Hin, W, Wh, WhH, n, K, 320, 0);
    attn_coef_kernel<<<(n * 32 + 255) / 256, 256>>>(Wh, avec, f1, f2, n);
    gat_attn_h_kernel<<<n, 320>>>(rp, ci, Wh, WhH, f1, f2, outp, add, n, mode);
}

extern "C" void kernel_launch(void* const* d_in, const int* in_sizes, int n_in,
                              void* d_out, int out_size) {
    const float* A = (const float*)d_in[0];
    const float* X = (const float*)d_in[1];
    const float* start_W = (const float*)d_in[2];
    const float* start_a = (const float*)d_in[3];
    const float* bottom_W = (const float*)d_in[4];
    const float* bottom_a = (const float*)d_in[5];
    const float* end_W = (const float*)d_in[6];
    const float* end_a = (const float*)d_in[7];
    const float* down_W = (const float*)d_in[8];
    const float* down_a = (const float*)d_in[9];
    const float* up_W = (const float*)d_in[10];
    const float* up_a = (const float*)d_in[11];
    const float* pool_w = (const float*)d_in[12];
    const float* pool_b = (const float*)d_in[13];
    const float* unpool_w = (const float*)d_in[14];
    const float* unpool_b = (const float*)d_in[15];
    float* outp = (float*)d_out;

    static const int ns[5] = {4096, 3686, 2580, 1548, 774};
    static const int sortP[4] = {4096, 4096, 4096, 2048};

    int* rp_base;
    int* ci_base;
    int* idx_base;
    int* rank_base;
    float *v, *XC, *Wh, *f1, *f2, *orgX, *downb, *Hbuf, *Ubuf, *scores, *vals;
    __half* WhH;
    cudaGetSymbolAddress((void**)&rp_base, g_rp);
    cudaGetSymbolAddress((void**)&ci_base, g_ci);
    cudaGetSymbolAddress((void**)&idx_base, g_idx);
    cudaGetSymbolAddress((void**)&rank_base, g_rankL);
    cudaGetSymbolAddress((void**)&v, g_v);
    cudaGetSymbolAddress((void**)&XC, g_XC);
    cudaGetSymbolAddress((void**)&Wh, g_Wh);
    cudaGetSymbolAddress((void**)&WhH, g_WhH);
    cudaGetSymbolAddress((void**)&f1, g_f1);
    cudaGetSymbolAddress((void**)&f2, g_f2);
    cudaGetSymbolAddress((void**)&orgX, g_orgX);
    cudaGetSymbolAddress((void**)&downb, g_down);
    cudaGetSymbolAddress((void**)&Hbuf, g_Hbuf);
    cudaGetSymbolAddress((void**)&Ubuf, g_Ubuf);
    cudaGetSymbolAddress((void**)&scores, g_scores);
    cudaGetSymbolAddress((void**)&vals, g_vals);

    int* rp0 = rp_base;
    int* ci0 = ci_base;

    // build level-0 CSR
    csr0_count<<<N0, 256>>>(A);
    scan_kernel<<<1, 1024>>>(rp0, N0);
    csr0_fill<<<N0, 256>>>(A, rp0, ci0);

    // eigenvector centrality: 30 power iterations, one persistent kernel
    centrality_fused<<<CBLOCKS, 1024>>>(rp0, ci0);

    // Xc = [X | centrality]
    concat_xc_kernel<<<(N0 * D + 255) / 256, 256>>>(X, v, XC);

    // start GAT -> orgX
    run_gat(XC, N0, D, start_W, start_a, rp0, ci0, orgX, 1, nullptr, Wh, WhH, f1, f2);

    // down path
    for (int i = 0; i < 4; i++) {
        int* rpi = rp_base + i * (N0 + 1);
        int* cii = ci_base + (size_t)i * NNZMAX;
        int* rpn = rp_base + (i + 1) * (N0 + 1);
        int* cin = ci_base + (size_t)(i + 1) * NNZMAX;
        int* idxi = idx_base + (size_t)i * N0;
        int* ranki = rank_base + (size_t)i * N0;
        float* dout = downb + (size_t)i * N0 * D;
        const float* Hin = (i == 0) ? orgX : Hbuf;
        run_gat(Hin, ns[i], D, down_W + (size_t)i * D * D, down_a + (size_t)i * 2 * D,
                rpi, cii, dout, 1, nullptr, Wh, WhH, f1, f2);
        // pool
        pool_score_kernel<<<(ns[i] * 32 + 255) / 256, 256>>>(dout, pool_w + (size_t)i * D,
                                                             pool_b + i, scores, ns[i]);
        sort_kernel<<<1, 1024>>>(scores, vals, idxi, ns[i], sortP[i]);
        poolx_kernel<<<(ns[i + 1] * D + 255) / 256, 256>>>(dout, idxi, vals, Hbuf, ns[i + 1]);
        rank_init_kernel<<<(ns[i] + 255) / 256, 256>>>(ranki, ns[i]);
        rank_set_kernel<<<(ns[i + 1] + 255) / 256, 256>>>(idxi, ranki, ns[i + 1]);
        pool_deg_kernel<<<(ns[i + 1] * 32 + 255) / 256, 256>>>(rpi, cii, idxi, ranki, ns[i + 1]);
        scan_kernel<<<1, 1024>>>(rpn, ns[i + 1]);
        pool_fill_kernel<<<(ns[i + 1] * 32 + 255) / 256, 256>>>(rpi, cii, rpn, cin, idxi,
                                                                ranki, ns[i + 1]);
    }

    // bottom GAT
    run_gat(Hbuf, ns[4], D, bottom_W, bottom_a, rp_base + 4 * (N0 + 1),
            ci_base + (size_t)4 * NNZMAX, Hbuf, 1, nullptr, Wh, WhH, f1, f2);

    // up path
    for (int i = 0; i < 4; i++) {
        int lu = 3 - i;
        int nl = ns[lu], nc = ns[lu + 1];
        int* rpl = rp_base + lu * (N0 + 1);
        int* cil = ci_base + (size_t)lu * NNZMAX;
        int* rankl = rank_base + (size_t)lu * N0;
        // gated = H * sigmoid(H @ unpool_w[i]^T + unpool_b[i]); fused scatter via rank map
        launch_gemm(Hbuf, unpool_w + (size_t)i * D * D, Wh, nullptr, nc, D, D, 1);
        unpool_fused_kernel<<<(nl * D + 255) / 256, 256>>>(Hbuf, Wh,
                                                           unpool_b + (size_t)i * D, rankl,
                                                           Ubuf, nl);
        // GAT + residual add of down_outs[lu]
        run_gat(Ubuf, nl, D, up_W + (size_t)i * D * D, up_a + (size_t)i * 2 * D, rpl, cil,
                Hbuf, 2, downb + (size_t)lu * N0 * D, Wh, WhH, f1, f2);
    }

    // end GAT on [H | orgX] with level-0 adjacency, no elu; concat fused into GEMM
    {
        dim3 gg((320 + 63) / 64, (N0 + 63) / 64);
        gemm_kernel<<<gg, 256>>>(Hbuf, orgX, 320, end_W, Wh, WhH, N0, 2 * D, 320, 0);
        attn_coef_kernel<<<(N0 * 32 + 255) / 256, 256>>>(Wh, end_a, f1, f2, N0);
        gat_attn_h_kernel<<<N0, 320>>>(rp0, ci0, Wh, WhH, f1, f2, outp, nullptr, N0, 0);
    }

    // second output: start_gat_outs
    cudaMemcpyAsync(outp + (size_t)N0 * D, orgX, (size_t)N0 * D * sizeof(float),
                    cudaMemcpyDeviceToDevice);
}

// round 14
// speedup vs baseline: 1.0695x; 1.0695x over previous
#include <cuda_runtime.h>
#include <cuda_fp16.h>
#include <math.h>
#include <stdint.h>

#define N0 4096
#define D 320
#define NNZMAX 2200000
#define CBLOCKS 128
#define CITERS 30

// ---------------- device global scratch (no allocation allowed) ----------------
__device__ int g_rp[5][N0 + 1];
__device__ int g_ci[5][NNZMAX];
__device__ int g_deg[N0 + 1];
__device__ __align__(16) float g_v[N0];
// write-once per-iteration power-iteration vectors (no L1 staleness: no line rewritten in-launch)
__device__ __align__(16) float g_pv[(CITERS + 1) * N0];
__device__ __align__(16) float g_XC[N0 * D];
__device__ __align__(16) float g_Wh[N0 * D];
__device__ __align__(16) __half g_WhH[N0 * D];
__device__ float g_f1[N0];
__device__ float g_f2[N0];
__device__ float g_f2max[1];
__device__ __align__(16) float g_orgX[N0 * D];
__device__ __align__(16) float g_down[4][N0 * D];
__device__ __align__(16) float g_Hbuf[N0 * D];
__device__ __align__(16) float g_Ubuf[N0 * D];
__device__ float g_scores[N0];
__device__ float g_vals[N0];
__device__ int g_idx[4][N0];
__device__ int g_rankL[4][N0];
__device__ unsigned g_barcnt = 0;
__device__ unsigned g_bargen = 0;

// ---------------- CSR build from dense A (level 0) ----------------
__global__ void csr0_count(const float* __restrict__ A) {
    int r = blockIdx.x;
    int cnt = 0;
    for (int c = threadIdx.x; c < N0; c += blockDim.x)
        cnt += (A[(size_t)r * N0 + c] > 0.f) ? 1 : 0;
    __shared__ int s[256];
    s[threadIdx.x] = cnt;
    __syncthreads();
    for (int st = 128; st > 0; st >>= 1) {
        if (threadIdx.x < st) s[threadIdx.x] += s[threadIdx.x + st];
        __syncthreads();
    }
    if (threadIdx.x == 0) g_deg[r] = s[0];
}

// single-block exclusive scan of g_deg[0..n) -> rp[0..n]
__global__ void scan_kernel(int* __restrict__ rp, int n) {
    __shared__ int sh[1024];
    int tid = threadIdx.x;
    int loc[4];
    int s = 0;
    int base = tid * 4;
#pragma unroll
    for (int k = 0; k < 4; k++) {
        int i = base + k;
        int vv = (i < n) ? g_deg[i] : 0;
        loc[k] = s;
        s += vv;
    }
    sh[tid] = s;
    __syncthreads();
    for (int off = 1; off < 1024; off <<= 1) {
        int v = (tid >= off) ? sh[tid - off] : 0;
        __syncthreads();
        sh[tid] += v;
        __syncthreads();
    }
    int pre = (tid > 0) ? sh[tid - 1] : 0;
#pragma unroll
    for (int k = 0; k < 4; k++) {
        int i = base + k;
        if (i < n) rp[i] = pre + loc[k];
    }
    if (tid == 1023) rp[n] = sh[1023];
}

__global__ void csr0_fill(const float* __restrict__ A, const int* __restrict__ rp,
                          int* __restrict__ ci) {
    int r = blockIdx.x;
    __shared__ int s_off;
    __shared__ int wcnt[8];
    if (threadIdx.x == 0) s_off = rp[r];
    __syncthreads();
    for (int c0 = 0; c0 < N0; c0 += 256) {
        int c = c0 + threadIdx.x;
        bool nz = (A[(size_t)r * N0 + c] > 0.f);
        unsigned b = __ballot_sync(0xffffffffu, nz);
        int lane = threadIdx.x & 31, w = threadIdx.x >> 5;
        if (lane == 0) wcnt[w] = __popc(b);
        __syncthreads();
        if (threadIdx.x == 0) {
            int a = s_off;
            for (int i = 0; i < 8; i++) {
                int t = wcnt[i];
                wcnt[i] = a;
                a += t;
            }
            s_off = a;
        }
        __syncthreads();
        if (nz) ci[wcnt[w] + __popc(b & ((1u << lane) - 1))] = c;
        __syncthreads();
    }
}

// ---------------- fused centrality (30 power iterations, one kernel) ----------------
__device__ __forceinline__ void grid_barrier() {
    __threadfence();
    __syncthreads();
    if (threadIdx.x == 0) {
        unsigned gen = *((volatile unsigned*)&g_bargen);
        unsigned t = atomicAdd(&g_barcnt, 1u);
        if (t == (unsigned)(CBLOCKS - 1)) {
            g_barcnt = 0;
            __threadfence();
            atomicAdd(&g_bargen, 1u);
        } else {
            while (*((volatile unsigned*)&g_bargen) == gen) {
            }
        }
    }
    __syncthreads();
    __threadfence();
}

__global__ void __launch_bounds__(1024, 1)
centrality_fused(const int* __restrict__ rp, const int* __restrict__ ci) {
    int tid = threadIdx.x;
    int w = tid >> 5, lane = tid & 31;
    int row = blockIdx.x * 32 + w;
    __shared__ float red[1024];
    // seed slice 0 = v0 = 1/N
    if (tid < 32) g_pv[blockIdx.x * 32 + tid] = 1.f / (float)N0;
    grid_barrier();
    float inv = 1.0f;  // multiply-by-1 is exact
    int s = rp[row], e = rp[row + 1];
    for (int t = 0; t < CITERS; t++) {
        const float* bufA = g_pv + (size_t)t * N0;
        float* bufB = g_pv + (size_t)(t + 1) * N0;
        // spmv: bufB[row] = sum_k fl(bufA[ci[k]] * inv)   (== v[ci[k]] of the unfused version)
        float acc = 0.f;
        for (int k = s + lane; k < e; k += 32) acc += __fmul_rn(bufA[ci[k]], inv);
        for (int o = 16; o; o >>= 1) acc += __shfl_down_sync(0xffffffffu, acc, o);
        if (lane == 0) bufB[row] = acc;
        grid_barrier();
        // norm of bufB: identical tree to the original norm_iter (redundant per block)
        float ss = 0.f;
        for (int i = tid; i < N0; i += 1024) {
            float tt = bufB[i];
            ss += tt * tt;
        }
        red[tid] = ss;
        __syncthreads();
        for (int st = 512; st > 0; st >>= 1) {
            if (tid < st) red[tid] += red[tid + st];
            __syncthreads();
        }
        inv = 1.f / (sqrtf(red[0]) + 1e-12f);
        __syncthreads();
    }
    if (tid < 32) {
        int i = blockIdx.x * 32 + tid;
        g_v[i] = __fmul_rn(g_pv[(size_t)CITERS * N0 + i], inv);
    }
}

// ---------------- misc elementwise ----------------
__global__ void concat_xc_kernel(const float* __restrict__ X, const float* __restrict__ v,
                                 float* __restrict__ XC) {
    int i = blockIdx.x * blockDim.x + threadIdx.x;
    if (i >= N0 * D) return;
    int r = i / D, d = i % D;
    XC[i] = (d < D - 1) ? X[(size_t)r * (D - 1) + d] : v[r];
}

// fused unpool: U[r,:] = rank[r]<0 ? 0 : H[rank[r],:] * sigmoid(Z[rank[r],:] + b)
__global__ void unpool_fused_kernel(const float* __restrict__ H, const float* __restrict__ Z,
                                    const float* __restrict__ b, const int* __restrict__ rank,
                                    float* __restrict__ U, int nl) {
    int i = blockIdx.x * blockDim.x + threadIdx.x;
    if (i >= nl * D) return;
    int r = i / D, d = i % D;
    int rk = rank[r];
    float o = 0.f;
    if (rk >= 0) {
        float z = Z[(size_t)rk * D + d] + b[d];
        o = H[(size_t)rk * D + d] * (1.f / (1.f + expf(-z)));
    }
    U[i] = o;
}

__global__ void poolx_kernel(const float* __restrict__ G, const int* __restrict__ idx,
                             const float* __restrict__ vals, float* __restrict__ nx, int nk) {
    int i = blockIdx.x * blockDim.x + threadIdx.x;
    if (i >= nk * D) return;
    int r = i / D, d = i % D;
    nx[i] = G[(size_t)idx[r] * D + d] * vals[r];
}

__global__ void rank_init_kernel(int* __restrict__ rank, int pn) {
    int i = blockIdx.x * blockDim.x + threadIdx.x;
    if (i < pn) rank[i] = -1;
}

__global__ void rank_set_kernel(const int* __restrict__ idx, int* __restrict__ rank, int nk) {
    int i = blockIdx.x * blockDim.x + threadIdx.x;
    if (i < nk) rank[idx[i]] = i;
}

// ---------------- pooled CSR build ----------------
__global__ void pool_deg_kernel(const int* __restrict__ prp, const int* __restrict__ pci,
                                const int* __restrict__ idx, const int* __restrict__ rank,
                                int nk) {
    int w = (blockIdx.x * blockDim.x + threadIdx.x) >> 5;
    if (w >= nk) return;
    int lane = threadIdx.x & 31;
    int p = idx[w];
    int s = prp[p], e = prp[p + 1];
    int cnt = 0;
    for (int k = s + lane; k < e; k += 32) cnt += (rank[pci[k]] >= 0) ? 1 : 0;
    for (int o = 16; o; o >>= 1) cnt += __shfl_down_sync(0xffffffffu, cnt, o);
    if (lane == 0) g_deg[w] = cnt;
}

__global__ void pool_fill_kernel(const int* __restrict__ prp, const int* __restrict__ pci,
                                 const int* __restrict__ nrp, int* __restrict__ nci,
                                 const int* __restrict__ idx, const int* __restrict__ rank,
                                 int nk) {
    int w = (blockIdx.x * blockDim.x + threadIdx.x) >> 5;
    if (w >= nk) return;
    int lane = threadIdx.x & 31;
    int p = idx[w];
    int s = prp[p], e = prp[p + 1];
    int wbase = nrp[w];
    for (int k0 = s; k0 < e; k0 += 32) {
        int k = k0 + lane;
        int rk = -1;
        if (k < e) rk = rank[pci[k]];
        bool keep = (rk >= 0);
        unsigned b = __ballot_sync(0xffffffffu, keep);
        if (keep) nci[wbase + __popc(b & ((1u << lane) - 1))] = rk;
        wbase += __popc(b);
    }
}

// ---------------- pool scoring + sort (top-k) ----------------
__global__ void pool_score_kernel(const float* __restrict__ Xf, const float* __restrict__ pw,
                                  const float* __restrict__ pb, float* __restrict__ scores, int n) {
    int w = (blockIdx.x * blockDim.x + threadIdx.x) >> 5;
    if (w >= n) return;
    int lane = threadIdx.x & 31;
    float s = 0.f;
    for (int d = lane; d < D; d += 32) s += Xf[(size_t)w * D + d] * pw[d];
    for (int o = 16; o; o >>= 1) s += __shfl_down_sync(0xffffffffu, s, o);
    if (lane == 0) {
        float z = (s + pb[0]) / 100.f;
        scores[w] = 1.f / (1.f + expf(-z));
    }
}

// single-block bitonic sort: descending score, ascending index on tie
__global__ void sort_kernel(const float* __restrict__ scores, float* __restrict__ vals,
                            int* __restrict__ idxo, int n, int P) {
    __shared__ float sv[4096];
    __shared__ int si[4096];
    int tid = threadIdx.x;
    for (int i = tid; i < P; i += 1024) {
        bool ok = (i < n);
        sv[i] = ok ? scores[i] : -INFINITY;
        si[i] = ok ? i : 0x7fffffff;
    }
    __syncthreads();
    for (int k = 2; k <= P; k <<= 1) {
        for (int j = k >> 1; j > 0; j >>= 1) {
            for (int i = tid; i < P; i += 1024) {
                int ixj = i ^ j;
                if (ixj > i) {
                    float s1 = sv[i], s2 = sv[ixj];
                    int i1 = si[i], i2 = si[ixj];
                    bool firstBetter = (s1 > s2) || (s1 == s2 && i1 < i2);
                    bool desc = ((i & k) == 0);
                    if (desc ? !firstBetter : firstBetter) {
                        sv[i] = s2;
                        sv[ixj] = s1;
                        si[i] = i2;
                        si[ixj] = i1;
                    }
                }
            }
            __syncthreads();
        }
    }
    for (int i = tid; i < n; i += 1024) {
        vals[i] = sv[i];
        idxo[i] = si[i];
    }
}

// ---------------- GEMM: C[M,N] = A[M,K] @ B ; B is [K,N] or (transB) [N,K] ----------------
// optional Ch: also store fp16 copy of C. A2: optional second A source for gk>=Ksplit.
__global__ void gemm_kernel(const float* __restrict__ A, const float* __restrict__ A2,
                            int Ksplit, const float* __restrict__ B,
                            float* __restrict__ C, __half* __restrict__ Ch,
                            int M, int K, int N, int transB) {
    __shared__ __align__(16) float As[16][68];
    __shared__ __align__(16) float Bs[16][68];
    int bm = blockIdx.y * 64, bn = blockIdx.x * 64;
    int tid = threadIdx.x;
    int tx = tid & 15, ty = tid >> 4;
    float acc[4][4] = {};
    for (int k0 = 0; k0 < K; k0 += 16) {
#pragma unroll
        for (int i = tid; i < 1024; i += 256) {
            int kk = i & 15, m = i >> 4;
            int gm = bm + m, gk = k0 + kk;
            float av = 0.f;
            if (gm < M) {
                if (gk < Ksplit)
                    av = A[(size_t)gm * Ksplit + gk];
                else
                    av = A2[(size_t)gm * Ksplit + (gk - Ksplit)];
            }
            As[kk][m] = av;
        }
        if (!transB) {
#pragma unroll
            for (int i = tid; i < 1024; i += 256) {
                int nn = i & 63, kk = i >> 6;
                int gn = bn + nn, gk = k0 + kk;
                Bs[kk][nn] = (gn < N) ? B[(size_t)gk * N + gn] : 0.f;
            }
        } else {
#pragma unroll
            for (int i = tid; i < 1024; i += 256) {
                int kk = i & 15, nn = i >> 4;
                int gn = bn + nn, gk = k0 + kk;
                Bs[kk][nn] = (gn < N) ? B[(size_t)gn * K + gk] : 0.f;
            }
        }
        __syncthreads();
#pragma unroll
        for (int kk = 0; kk < 16; kk++) {
            float4 a4 = *reinterpret_cast<const float4*>(&As[kk][ty * 4]);
            float4 b4 = *reinterpret_cast<const float4*>(&Bs[kk][tx * 4]);
            float av[4] = {a4.x, a4.y, a4.z, a4.w};
            float bv[4] = {b4.x, b4.y, b4.z, b4.w};
#pragma unroll
            for (int i2 = 0; i2 < 4; i2++)
#pragma unroll
                for (int j2 = 0; j2 < 4; j2++) acc[i2][j2] += av[i2] * bv[j2];
        }
        __syncthreads();
    }
#pragma unroll
    for (int i2 = 0; i2 < 4; i2++) {
        int gm = bm + ty * 4 + i2;
        if (gm < M) {
#pragma unroll
            for (int j2 = 0; j2 < 4; j2++) {
                int gn = bn + tx * 4 + j2;
                if (gn < N) {
                    C[(size_t)gm * N + gn] = acc[i2][j2];
                    if (Ch) Ch[(size_t)gm * N + gn] = __float2half(acc[i2][j2]);
                }
            }
        }
    }
}

// 32x64 tile variant for small M (better wave balance)
__global__ void gemm32_kernel(const float* __restrict__ A, const float* __restrict__ B,
                              float* __restrict__ C, __half* __restrict__ Ch,
                              int M, int K, int N, int transB) {
    __shared__ __align__(16) float As[16][36];
    __shared__ __align__(16) float Bs[16][68];
    int bm = blockIdx.y * 32, bn = blockIdx.x * 64;
    int tid = threadIdx.x;
    int tx = tid & 15, ty = tid >> 4;
    float acc[2][4] = {};
    for (int k0 = 0; k0 < K; k0 += 16) {
#pragma unroll
        for (int i = tid; i < 512; i += 256) {
            int kk = i & 15, m = i >> 4;
            int gm = bm + m, gk = k0 + kk;
            As[kk][m] = (gm < M) ? A[(size_t)gm * K + gk] : 0.f;
        }
        if (!transB) {
#pragma unroll
            for (int i = tid; i < 1024; i += 256) {
                int nn = i & 63, kk = i >> 6;
                int gn = bn + nn, gk = k0 + kk;
                Bs[kk][nn] = (gn < N) ? B[(size_t)gk * N + gn] : 0.f;
            }
        } else {
#pragma unroll
            for (int i = tid; i < 1024; i += 256) {
                int kk = i & 15, nn = i >> 4;
                int gn = bn + nn, gk = k0 + kk;
                Bs[kk][nn] = (gn < N) ? B[(size_t)gn * K + gk] : 0.f;
            }
        }
        __syncthreads();
#pragma unroll
        for (int kk = 0; kk < 16; kk++) {
            float a0 = As[kk][ty * 2];
            float a1 = As[kk][ty * 2 + 1];
            float4 b4 = *reinterpret_cast<const float4*>(&Bs[kk][tx * 4]);
            float bv[4] = {b4.x, b4.y, b4.z, b4.w};
#pragma unroll
            for (int j2 = 0; j2 < 4; j2++) {
                acc[0][j2] += a0 * bv[j2];
                acc[1][j2] += a1 * bv[j2];
            }
        }
        __syncthreads();
    }
#pragma unroll
    for (int i2 = 0; i2 < 2; i2++) {
        int gm = bm + ty * 2 + i2;
        if (gm < M) {
#pragma unroll
            for (int j2 = 0; j2 < 4; j2++) {
                int gn = bn + tx * 4 + j2;
                if (gn < N) {
                    C[(size_t)gm * N + gn] = acc[i2][j2];
                    if (Ch) Ch[(size_t)gm * N + gn] = __float2half(acc[i2][j2]);
                }
            }
        }
    }
}

// ---------------- attention coefficients: f1 = Wh@a[:D], f2 = Wh@a[D:] ----------------
__global__ void attn_coef_kernel(const float* __restrict__ Wh, const float* __restrict__ a,
                                 float* __restrict__ f1, float* __restrict__ f2, int n) {
    int w = (blockIdx.x * blockDim.x + threadIdx.x) >> 5;
    if (w >= n) return;
    int lane = threadIdx.x & 31;
    float s1 = 0.f, s2 = 0.f;
    for (int d = lane; d < D; d += 32) {
        float v = Wh[(size_t)w * D + d];
        s1 += v * a[d];
        s2 += v * a[D + d];
    }
    for (int o = 16; o; o >>= 1) {
        s1 += __shfl_down_sync(0xffffffffu, s1, o);
        s2 += __shfl_down_sync(0xffffffffu, s2, o);
    }
    if (lane == 0) {
        f1[w] = s1;
        f2[w] = s2;
    }
}

// global max of f2 (exact max: order-independent, deterministic)
__global__ void f2max_kernel(const float* __restrict__ f2, float* __restrict__ fm, int n) {
    __shared__ float red[256];
    float m = -INFINITY;
    for (int i = threadIdx.x; i < n; i += 256) m = fmaxf(m, f2[i]);
    red[threadIdx.x] = m;
    __syncthreads();
    for (int st = 128; st > 0; st >>= 1) {
        if (threadIdx.x < st) red[threadIdx.x] = fmaxf(red[threadIdx.x], red[threadIdx.x + st]);
        __syncthreads();
    }
    if (threadIdx.x == 0) fm[0] = red[0];
}

// fp16 row accumulate helper: adds p * row (8 halves in a uint4) into acc[8], in order
__device__ __forceinline__ void acc_row8(float* acc, uint4 hv, float pj) {
    __half2 h0 = *reinterpret_cast<__half2*>(&hv.x);
    __half2 h1 = *reinterpret_cast<__half2*>(&hv.y);
    __half2 h2 = *reinterpret_cast<__half2*>(&hv.z);
    __half2 h3 = *reinterpret_cast<__half2*>(&hv.w);
    float2 f0 = __half22float2(h0);
    float2 fb = __half22float2(h1);
    float2 fc = __half22float2(h2);
    float2 fd = __half22float2(h3);
    acc[0] += pj * f0.x;
    acc[1] += pj * f0.y;
    acc[2] += pj * fb.x;
    acc[3] += pj * fb.y;
    acc[4] += pj * fc.x;
    acc[5] += pj * fc.y;
    acc[6] += pj * fd.x;
    acc[7] += pj * fd.y;
}

// ---------------- fused sparse masked softmax + SpMM GAT attention (fp16 values) ----------------
// SINGLE PASS over edges: uses upper bound m' = lrelu(f1_r + max_all(f2)) >= all e_rc
// instead of the exact row max. softmax(e - m') == softmax(e - m) mathematically
// (constant factor cancels in p/Z); exp args stay in [-~60, 0] -> no under/overflow.
// Softmax weights / reductions stay fp32; only gathered neighbor rows are fp16.
// mode: 0 = plain, 1 = elu, 2 = elu + residual add
__global__ void gat_attn_h_kernel(const int* __restrict__ rp, const int* __restrict__ ci,
                                  const float* __restrict__ Wh, const __half* __restrict__ WhH,
                                  const float* __restrict__ f1, const float* __restrict__ f2,
                                  const float* __restrict__ f2m, float* __restrict__ out,
                                  const float* __restrict__ addsrc, int n, int mode) {
    int r = blockIdx.x;
    int tid = threadIdx.x;
    __shared__ float s_red[320];
    __shared__ float s_p[320];
    __shared__ int s_c[320];
    __shared__ float s_accf[8 * 320];
    int start = rp[r];
    int deg = rp[r + 1] - start;
    if (deg == 0) {
        float s = 0.f;
        for (int i = 0; i < n; i++) s += Wh[(size_t)i * D + tid];
        float o = s / (float)n;
        if (mode >= 1) o = (o > 0.f) ? o : expm1f(o);
        if (mode == 2) o += addsrc[(size_t)r * D + tid];
        out[(size_t)r * D + tid] = o;
        return;
    }
    float F1 = f1[r];
    // per-row upper bound on e = lrelu(F1 + f2[c]) via global max of f2 (lrelu monotonic)
    float eb = F1 + f2m[0];
    float m = (eb > 0.f) ? eb : 0.2f * eb;
    int g = tid / 40, l = tid % 40;
    float acc[8];
#pragma unroll
    for (int c = 0; c < 8; c++) acc[c] = 0.f;
    float Zp = 0.f;
    for (int b0 = 0; b0 < deg; b0 += 320) {
        int k = b0 + tid;
        float p = 0.f;
        int c = 0;
        if (k < deg) {
            c = ci[start + k];
            float e = F1 + f2[c];
            e = (e > 0.f) ? e : 0.2f * e;
            p = __expf(e - m);
        }
        s_p[tid] = p;
        s_c[tid] = c;
        Zp += p;
        __syncthreads();
        int cnt = min(320, deg - b0);
        // 4-wide manual unroll: 4 independent LDG.128 in flight per step.
        int j = g;
#pragma unroll 1
        for (; j + 24 < cnt; j += 32) {
            float p0 = s_p[j];
            float p1 = s_p[j + 8];
            float p2 = s_p[j + 16];
            float p3 = s_p[j + 24];
            const uint4* r0 = reinterpret_cast<const uint4*>(WhH + (size_t)s_c[j] * D);
            const uint4* r1 = reinterpret_cast<const uint4*>(WhH + (size_t)s_c[j + 8] * D);
            const uint4* r2 = reinterpret_cast<const uint4*>(WhH + (size_t)s_c[j + 16] * D);
            const uint4* r3 = reinterpret_cast<const uint4*>(WhH + (size_t)s_c[j + 24] * D);
            uint4 hv0 = r0[l];
            uint4 hv1 = r1[l];
            uint4 hv2 = r2[l];
            uint4 hv3 = r3[l];
            acc_row8(acc, hv0, p0);
            acc_row8(acc, hv1, p1);
            acc_row8(acc, hv2, p2);
            acc_row8(acc, hv3, p3);
        }
#pragma unroll 1
        for (; j < cnt; j += 8) {
            float pj = s_p[j];
            const uint4* row = reinterpret_cast<const uint4*>(WhH + (size_t)s_c[j] * D);
            uint4 hv = row[l];
            acc_row8(acc, hv, pj);
        }
        __syncthreads();
    }
    s_red[tid] = Zp;
    __syncthreads();
    if (tid < 64) s_red[tid] += s_red[tid + 256];
    __syncthreads();
    if (tid < 128) s_red[tid] += s_red[tid + 128];
    __syncthreads();
    if (tid < 64) s_red[tid] += s_red[tid + 64];
    __syncthreads();
    if (tid < 32) {
        float v = s_red[tid] + s_red[tid + 32];
        for (int o = 16; o; o >>= 1) v += __shfl_down_sync(0xffffffffu, v, o);
        if (tid == 0) s_red[0] = v;
    }
    __syncthreads();
    float invZ = 1.f / s_red[0];
#pragma unroll
    for (int c = 0; c < 8; c++) s_accf[g * 320 + l * 8 + c] = acc[c];
    __syncthreads();
    {
        int d = tid;
        float o = 0.f;
#pragma unroll
        for (int gg2 = 0; gg2 < 8; gg2++) o += s_accf[gg2 * 320 + d];
        o *= invZ;
        if (mode >= 1) o = (o > 0.f) ? o : expm1f(o);
        if (mode == 2) o += addsrc[(size_t)r * D + d];
        out[(size_t)r * D + d] = o;
    }
}

// ---------------- host ----------------
static void launch_gemm(const float* A, const float* B, float* C, __half* Ch, int M, int K,
                        int N, int transB) {
    if (M < 2048) {
        dim3 gg((N + 63) / 64, (M + 31) / 32);
        gemm32_kernel<<<gg, 256>>>(A, B, C, Ch, M, K, N, transB);
    } else {
        dim3 gg((N + 63) / 64, (M + 63) / 64);
        gemm_kernel<<<gg, 256>>>(A, nullptr, K, B, C, Ch, M, K, N, transB);
    }
}

static float* s_f2max_ptr;

static void run_gat(const float* Hin, int n, int K, const float* W, const float* avec,
                    const int* rp, const int* ci, float* outp, int mode, const float* add,
                    float* Wh, __half* WhH, float* f1, float* f2) {
    launch_gemm(Hin, W, Wh, WhH, n, K, 320, 0);
    attn_coef_kernel<<<(n * 32 + 255) / 256, 256>>>(Wh, avec, f1, f2, n);
    f2max_kernel<<<1, 256>>>(f2, s_f2max_ptr, n);
    gat_attn_h_kernel<<<n, 320>>>(rp, ci, Wh, WhH, f1, f2, s_f2max_ptr, outp, add, n, mode);
}

extern "C" void kernel_launch(void* const* d_in, const int* in_sizes, int n_in,
                              void* d_out, int out_size) {
    const float* A = (const float*)d_in[0];
    const float* X = (const float*)d_in[1];
    const float* start_W = (const float*)d_in[2];
    const float* start_a = (const float*)d_in[3];
    const float* bottom_W = (const float*)d_in[4];
    const float* bottom_a = (const float*)d_in[5];
    const float* end_W = (const float*)d_in[6];
    const float* end_a = (const float*)d_in[7];
    const float* down_W = (const float*)d_in[8];
    const float* down_a = (const float*)d_in[9];
    const float* up_W = (const float*)d_in[10];
    const float* up_a = (const float*)d_in[11];
    const float* pool_w = (const float*)d_in[12];
    const float* pool_b = (const float*)d_in[13];
    const float* unpool_w = (const float*)d_in[14];
    const float* unpool_b = (const float*)d_in[15];
    float* outp = (float*)d_out;

    static const int ns[5] = {4096, 3686, 2580, 1548, 774};
    static const int sortP[4] = {4096, 4096, 4096, 2048};

    int* rp_base;
    int* ci_base;
    int* idx_base;
    int* rank_base;
    float *v, *XC, *Wh, *f1, *f2, *orgX, *downb, *Hbuf, *Ubuf, *scores, *vals;
    __half* WhH;
    cudaGetSymbolAddress((void**)&rp_base, g_rp);
    cudaGetSymbolAddress((void**)&ci_base, g_ci);
    cudaGetSymbolAddress((void**)&idx_base, g_idx);
    cudaGetSymbolAddress((void**)&rank_base, g_rankL);
    cudaGetSymbolAddress((void**)&v, g_v);
    cudaGetSymbolAddress((void**)&XC, g_XC);
    cudaGetSymbolAddress((void**)&Wh, g_Wh);
    cudaGetSymbolAddress((void**)&WhH, g_WhH);
    cudaGetSymbolAddress((void**)&f1, g_f1);
    cudaGetSymbolAddress((void**)&f2, g_f2);
    cudaGetSymbolAddress((void**)&s_f2max_ptr, g_f2max);
    cudaGetSymbolAddress((void**)&orgX, g_orgX);
    cudaGetSymbolAddress((void**)&downb, g_down);
    cudaGetSymbolAddress((void**)&Hbuf, g_Hbuf);
    cudaGetSymbolAddress((void**)&Ubuf, g_Ubuf);
    cudaGetSymbolAddress((void**)&scores, g_scores);
    cudaGetSymbolAddress((void**)&vals, g_vals);

    int* rp0 = rp_base;
    int* ci0 = ci_base;

    // build level-0 CSR
    csr0_count<<<N0, 256>>>(A);
    scan_kernel<<<1, 1024>>>(rp0, N0);
    csr0_fill<<<N0, 256>>>(A, rp0, ci0);

    // eigenvector centrality: 30 power iterations, one persistent kernel
    centrality_fused<<<CBLOCKS, 1024>>>(rp0, ci0);

    // Xc = [X | centrality]
    concat_xc_kernel<<<(N0 * D + 255) / 256, 256>>>(X, v, XC);

    // start GAT -> orgX
    run_gat(XC, N0, D, start_W, start_a, rp0, ci0, orgX, 1, nullptr, Wh, WhH, f1, f2);

    // down path
    for (int i = 0; i < 4; i++) {
        int* rpi = rp_base + i * (N0 + 1);
        int* cii = ci_base + (size_t)i * NNZMAX;
        int* rpn = rp_base + (i + 1) * (N0 + 1);
        int* cin = ci_base + (size_t)(i + 1) * NNZMAX;
        int* idxi = idx_base + (size_t)i * N0;
        int* ranki = rank_base + (size_t)i * N0;
        float* dout = downb + (size_t)i * N0 * D;
        const float* Hin = (i == 0) ? orgX : Hbuf;
        run_gat(Hin, ns[i], D, down_W + (size_t)i * D * D, down_a + (size_t)i * 2 * D,
                rpi, cii, dout, 1, nullptr, Wh, WhH, f1, f2);
        // pool
        pool_score_kernel<<<(ns[i] * 32 + 255) / 256, 256>>>(dout, pool_w + (size_t)i * D,
                                                             pool_b + i, scores, ns[i]);
        sort_kernel<<<1, 1024>>>(scores, vals, idxi, ns[i], sortP[i]);
        poolx_kernel<<<(ns[i + 1] * D + 255) / 256, 256>>>(dout, idxi, vals, Hbuf, ns[i + 1]);
        rank_init_kernel<<<(ns[i] + 255) / 256, 256>>>(ranki, ns[i]);
        rank_set_kernel<<<(ns[i + 1] + 255) / 256, 256>>>(idxi, ranki, ns[i + 1]);
        pool_deg_kernel<<<(ns[i + 1] * 32 + 255) / 256, 256>>>(rpi, cii, idxi, ranki, ns[i + 1]);
        scan_kernel<<<1, 1024>>>(rpn, ns[i + 1]);
        pool_fill_kernel<<<(ns[i + 1] * 32 + 255) / 256, 256>>>(rpi, cii, rpn, cin, idxi,
                                                                ranki, ns[i + 1]);
    }

    // bottom GAT
    run_gat(Hbuf, ns[4], D, bottom_W, bottom_a, rp_base + 4 * (N0 + 1),
            ci_base + (size_t)4 * NNZMAX, Hbuf, 1, nullptr, Wh, WhH, f1, f2);

    // up path
    for (int i = 0; i < 4; i++) {
        int lu = 3 - i;
        int nl = ns[lu], nc = ns[lu + 1];
        int* rpl = rp_base + lu * (N0 + 1);
        int* cil = ci_base + (size_t)lu * NNZMAX;
        int* rankl = rank_base + (size_t)lu * N0;
        // gated = H * sigmoid(H @ unpool_w[i]^T + unpool_b[i]); fused scatter via rank map
        launch_gemm(Hbuf, unpool_w + (size_t)i * D * D, Wh, nullptr, nc, D, D, 1);
        unpool_fused_kernel<<<(nl * D + 255) / 256, 256>>>(Hbuf, Wh,
                                                           unpool_b + (size_t)i * D, rankl,
                                                           Ubuf, nl);
        // GAT + residual add of down_outs[lu]
        run_gat(Ubuf, nl, D, up_W + (size_t)i * D * D, up_a + (size_t)i * 2 * D, rpl, cil,
                Hbuf, 2, downb + (size_t)lu * N0 * D, Wh, WhH, f1, f2);
    }

    // end GAT on [H | orgX] with level-0 adjacency, no elu; concat fused into GEMM
    {
        dim3 gg((320 + 63) / 64, (N0 + 63) / 64);
        gemm_kernel<<<gg, 256>>>(Hbuf, orgX, 320, end_W, Wh, WhH, N0, 2 * D, 320, 0);
        attn_coef_kernel<<<(N0 * 32 + 255) / 256, 256>>>(Wh, end_a, f1, f2, N0);
        f2max_kernel<<<1, 256>>>(f2, s_f2max_ptr, N0);
        gat_attn_h_kernel<<<N0, 320>>>(rp0, ci0, Wh, WhH, f1, f2, s_f2max_ptr, outp, nullptr,
                                       N0, 0);
    }

    // second output: start_gat_outs
    cudaMemcpyAsync(outp + (size_t)N0 * D, orgX, (size_t)N0 * D * sizeof(float),
                    cudaMemcpyDeviceToDevice);
}